// round 3
// baseline (speedup 1.0000x reference)
#include <cuda_runtime.h>

#define NN     5000
#define NE     160000
#define HID    64
#define BATCH  512
#define GRID   148
#define NT     512
#define TOTAL  (GRID * NT)
#define CH     34            // scan chunk per block (148*34 = 5032 >= 5000)

// ---------------- scratch (device globals: allocation-free) ----------------
__device__ int   g_cnt[NN];
__device__ int   g_rowptr[NN + 1];
__device__ int   g_cur[NN];
__device__ int   g_esrc[NE];
__device__ __align__(16) float g_h1[NN * HID];
__device__ __align__(16) float g_h2[NN * HID];
__device__ __align__(16) float g_hp[5120 * HID];   // pad rows [5000,5120) stay 0 forever
__device__ __align__(16) float g_tp[BATCH * HID];
__device__ unsigned g_det[GRID];
__device__ int      g_bsum[GRID];
__device__ unsigned g_bar_count = 0;
__device__ volatile unsigned g_bar_gen = 0;

union U64 { unsigned long long u; float2 f; };

__device__ __forceinline__ unsigned long long pack2(float a, float b) {
    unsigned long long r;
    asm("mov.b64 %0, {%1, %2};" : "=l"(r) : "f"(a), "f"(b));
    return r;
}

// -------- software grid barrier (all GRID blocks co-resident by construction) --------
__device__ __forceinline__ void grid_sync() {
    __syncthreads();
    if (threadIdx.x == 0) {
        __threadfence();                       // release (+ gpu-scope = CCTL.IVALL)
        unsigned gen = g_bar_gen;
        if (atomicAdd(&g_bar_count, 1) == GRID - 1) {
            g_bar_count = 0;
            __threadfence();
            g_bar_gen = gen + 1;
        } else {
            while (g_bar_gen == gen) __nanosleep(64);
        }
        __threadfence();                       // acquire: invalidate L1 before phase reads
    }
    __syncthreads();
}

// -------- task MLP, one warp per batch, shuffle-based (no block sync) --------
__device__ __forceinline__ void do_task(int b, int lane, const float* __restrict__ tf,
                                        const float* __restrict__ Wt1, const float* __restrict__ bt1,
                                        const float* __restrict__ Wt2, const float* __restrict__ bt2,
                                        const float* __restrict__ Wc1, const float* __restrict__ bc1) {
    float4 f = *(const float4*)(tf + (size_t)b * 4);
    int o0 = lane, o1 = lane + 32;
    float a0 = bt1[o0] + Wt1[o0*4]*f.x + Wt1[o0*4+1]*f.y + Wt1[o0*4+2]*f.z + Wt1[o0*4+3]*f.w;
    float a1 = bt1[o1] + Wt1[o1*4]*f.x + Wt1[o1*4+1]*f.y + Wt1[o1*4+2]*f.z + Wt1[o1*4+3]*f.w;
    a0 = fmaxf(a0, 0.f); a1 = fmaxf(a1, 0.f);

    float c0 = bt2[o0], c1 = bt2[o1];
#pragma unroll
    for (int h = 0; h < 32; h++) {
        float v = __shfl_sync(0xffffffffu, a0, h);
        c0 += Wt2[o0*64 + h] * v;
        c1 += Wt2[o1*64 + h] * v;
    }
#pragma unroll
    for (int h = 0; h < 32; h++) {
        float v = __shfl_sync(0xffffffffu, a1, h);
        c0 += Wt2[o0*64 + 32 + h] * v;
        c1 += Wt2[o1*64 + 32 + h] * v;
    }

    float d0 = bc1[o0], d1 = bc1[o1];
#pragma unroll
    for (int h = 0; h < 32; h++) {
        float v = __shfl_sync(0xffffffffu, c0, h);
        d0 += Wc1[o0*128 + 64 + h] * v;
        d1 += Wc1[o1*128 + 64 + h] * v;
    }
#pragma unroll
    for (int h = 0; h < 32; h++) {
        float v = __shfl_sync(0xffffffffu, c1, h);
        d0 += Wc1[o0*128 + 96 + h] * v;
        d1 += Wc1[o1*128 + 96 + h] * v;
    }
    g_tp[b*64 + o0] = d0;
    g_tp[b*64 + o1] = d1;
}

// ---------------- the single persistent kernel ----------------
__global__ void __launch_bounds__(NT, 1)
k_all(const float* __restrict__ x,   const void* __restrict__ ei,  const float* __restrict__ tf,
      const float* __restrict__ Wl1, const float* __restrict__ bl1, const float* __restrict__ Wr1,
      const float* __restrict__ Wl2, const float* __restrict__ bl2, const float* __restrict__ Wr2,
      const float* __restrict__ Wt1, const float* __restrict__ bt1,
      const float* __restrict__ Wt2, const float* __restrict__ bt2,
      const float* __restrict__ Wc1, const float* __restrict__ bc1,
      const float* __restrict__ Wc2, const float* __restrict__ bc2,
      float* __restrict__ out) {
    __shared__ union {
        struct { float Wl[64*65]; float Wr[64*65]; float mean[8][64]; float xx[8][64]; } l2;
        struct { float W[64*65]; } hp;
        struct { float hp[64*129]; float tp[64*32]; unsigned long long w2[64]; } fin;
    } sm;
    __shared__ unsigned s_det[16];
    __shared__ int s_i32;

    const int tid  = threadIdx.x;
    const int bx   = blockIdx.x;
    const int gt   = bx * NT + tid;
    const int lane = tid & 31;
    const int wid  = tid >> 5;
    const int gw   = bx * 16 + wid;

    // ---- Phase A: zero histogram + detect edge dtype ----
    for (int i = gt; i < NN; i += TOTAL) g_cnt[i] = 0;
    {
        const unsigned* w = (const unsigned*)ei;   // safe window: first 2*NE u32 words
        unsigned acc = 0;
        for (int i = gt; i < NE; i += TOTAL) acc |= w[2*i + 1];
        acc = __reduce_or_sync(0xffffffffu, acc);
        if (lane == 0) s_det[wid] = acc;
    }
    __syncthreads();
    if (tid == 0) {
        unsigned a = 0;
#pragma unroll
        for (int i = 0; i < 16; i++) a |= s_det[i];
        g_det[bx] = a;
    }
    grid_sync();
    if (tid == 0) {
        unsigned a = 0;
        for (int i = 0; i < GRID; i++) a |= g_det[i];
        s_i32 = (a != 0);
    }
    __syncthreads();
    const int i32 = s_i32;

    // ---- Phase B: degree histogram + task MLP (independent, overlapped) ----
    for (int e = gt; e < NE; e += TOTAL) {
        int d = i32 ? ((const int*)ei)[NE + e] : (int)((const long long*)ei)[NE + e];
        atomicAdd(&g_cnt[d], 1);
    }
    if (gw < BATCH) do_task(gw, lane, tf, Wt1, bt1, Wt2, bt2, Wc1, bc1);
    grid_sync();

    // ---- Phase C1: per-block chunk sums ----
    if (tid == 0) {
        int i0 = bx * CH, s = 0;
#pragma unroll
        for (int i = 0; i < CH; i++) { int n = i0 + i; s += (n < NN) ? g_cnt[n] : 0; }
        g_bsum[bx] = s;
    }
    grid_sync();

    // ---- Phase C2: rowptr via redundant base scan ----
    if (tid == 0) {
        int base = 0;
        for (int j = 0; j < bx; j++) base += g_bsum[j];
        int i0 = bx * CH, run = base;
        for (int i = 0; i < CH; i++) {
            int n = i0 + i;
            if (n < NN) {
                g_rowptr[n] = run; g_cur[n] = run;
                run += g_cnt[n];
                if (n == NN - 1) g_rowptr[NN] = run;
            }
        }
    }
    grid_sync();

    // ---- Phase D: CSR fill ----
    for (int e = gt; e < NE; e += TOTAL) {
        int s, d;
        if (i32) { const int* p = (const int*)ei; s = p[e]; d = p[NE + e]; }
        else     { const long long* p = (const long long*)ei; s = (int)p[e]; d = (int)p[NE + e]; }
        g_esrc[atomicAdd(&g_cur[d], 1)] = s;
    }
    grid_sync();

    // ---- Phase E: layer-1 SAGE (warp per node) ----
    for (int n = gw; n < NN; n += GRID * 16) {
        int start = g_rowptr[n], end = g_rowptr[n + 1];
        float4 a = make_float4(0.f, 0.f, 0.f, 0.f);
        for (int e = start + lane; e < end; e += 32) {
            float4 xv = *(const float4*)(x + (size_t)g_esrc[e] * 4);
            a.x += xv.x; a.y += xv.y; a.z += xv.z; a.w += xv.w;
        }
#pragma unroll
        for (int off = 16; off; off >>= 1) {
            a.x += __shfl_xor_sync(0xffffffffu, a.x, off);
            a.y += __shfl_xor_sync(0xffffffffu, a.y, off);
            a.z += __shfl_xor_sync(0xffffffffu, a.z, off);
            a.w += __shfl_xor_sync(0xffffffffu, a.w, off);
        }
        float invd = 1.f / fmaxf((float)(end - start), 1.f);
        float m0 = a.x*invd, m1 = a.y*invd, m2 = a.z*invd, m3 = a.w*invd;
        float4 xn = *(const float4*)(x + (size_t)n * 4);
#pragma unroll
        for (int k = 0; k < 2; k++) {
            int o = lane + 32 * k;
            float v = bl1[o]
                    + Wl1[o*4]*m0 + Wl1[o*4+1]*m1 + Wl1[o*4+2]*m2 + Wl1[o*4+3]*m3
                    + Wr1[o*4]*xn.x + Wr1[o*4+1]*xn.y + Wr1[o*4+2]*xn.z + Wr1[o*4+3]*xn.w;
            g_h1[n*64 + o] = fmaxf(v, 0.f);
        }
    }
    grid_sync();

    // ---- Phase F: layer-2 SAGE (8 groups of 64 per block, 5 sweeps) ----
    {
        const int g = tid >> 6, o = tid & 63;
        for (int idx = tid; idx < 4096; idx += NT) {
            int r = idx >> 6, c = idx & 63;        // r = out, c = in
            sm.l2.Wl[c*65 + r] = Wl2[idx];
            sm.l2.Wr[c*65 + r] = Wr2[idx];
        }
        float bias2 = bl2[o];
        __syncthreads();
        for (int ni = 0; ni < 5; ni++) {
            int n = (ni * GRID + bx) * 8 + g;
            bool ok = (n < NN);
            if (ok) {
                int start = g_rowptr[n], end = g_rowptr[n + 1];
                float s = 0.f;
#pragma unroll 4
                for (int e = start; e < end; e++) s += g_h1[g_esrc[e]*64 + o];
                sm.l2.mean[g][o] = s / fmaxf((float)(end - start), 1.f);
                sm.l2.xx[g][o]   = g_h1[n*64 + o];
            }
            __syncthreads();
            if (ok) {
                float acc = bias2;
#pragma unroll
                for (int h = 0; h < 64; h++)
                    acc += sm.l2.Wl[h*65 + o] * sm.l2.mean[g][h]
                         + sm.l2.Wr[h*65 + o] * sm.l2.xx[g][h];
                g_h2[n*64 + o] = fmaxf(acc, 0.f);
            }
            __syncthreads();
        }
    }
    grid_sync();

    // ---- Phase G: h_part = h2 @ Wc1[:, :64]^T ----
    for (int idx = tid; idx < 4096; idx += NT) {
        int r = idx >> 6, c = idx & 63;
        sm.hp.W[c*65 + r] = Wc1[r*128 + c];
    }
    __syncthreads();
    for (int t = gt; t < NN * 64; t += TOTAL) {
        int n = t >> 6, oo = t & 63;
        const float4* row = (const float4*)(g_h2 + (size_t)n * 64);
        float acc = 0.f;
#pragma unroll
        for (int h4 = 0; h4 < 16; h4++) {
            float4 v = row[h4];
            acc += sm.hp.W[(4*h4+0)*65 + oo] * v.x + sm.hp.W[(4*h4+1)*65 + oo] * v.y
                 + sm.hp.W[(4*h4+2)*65 + oo] * v.z + sm.hp.W[(4*h4+3)*65 + oo] * v.w;
        }
        g_hp[t] = acc;
    }
    grid_sync();

    // ---- Phase H: final scores, persistent tiles of 128 nodes x 32 batches ----
    {
        const int nl = tid & 127;
        const int q  = tid >> 7;          // 0..3: batch quarter
        for (int t = bx; t < 640; t += GRID) {
            __syncthreads();              // protect smem reuse across tiles
            int tn = t % 40, tb = t / 40;
            int n0 = tn * 128, b0 = tb * 32;
            for (int idx = tid; idx < 8192; idx += NT) {
                int r = idx >> 6, h = idx & 63;
                sm.fin.hp[h*129 + r] = g_hp[(size_t)(n0 + r) * 64 + h];
            }
            for (int idx = tid; idx < 2048; idx += NT) {
                int r = idx >> 6, h = idx & 63;
                sm.fin.tp[h*32 + r] = g_tp[(size_t)(b0 + r) * 64 + h];
            }
            if (tid < 64) { float w = Wc2[tid]; sm.fin.w2[tid] = pack2(w, w); }
            __syncthreads();

            U64 acc[4];
#pragma unroll
            for (int p = 0; p < 4; p++) acc[p].u = 0ull;

            for (int h = 0; h < 64; h++) {
                float hv = sm.fin.hp[h*129 + nl];
                unsigned long long hv2 = pack2(hv, hv);
                unsigned long long w2  = sm.fin.w2[h];
                const unsigned long long* tp =
                    (const unsigned long long*)(sm.fin.tp + h*32 + q*8);
#pragma unroll
                for (int p = 0; p < 4; p++) {
                    U64 a;
                    asm("add.rn.f32x2 %0, %1, %2;" : "=l"(a.u) : "l"(tp[p]), "l"(hv2));
                    a.f.x = fmaxf(a.f.x, 0.f);
                    a.f.y = fmaxf(a.f.y, 0.f);
                    asm("fma.rn.f32x2 %0, %1, %2, %0;" : "+l"(acc[p].u) : "l"(a.u), "l"(w2));
                }
            }

            int n = n0 + nl;
            if (n < NN) {
                float bias = bc2[0];
#pragma unroll
                for (int p = 0; p < 4; p++) {
                    int b = b0 + q*8 + 2*p;
                    out[(size_t)b       * NN + n] = acc[p].f.x + bias;
                    out[(size_t)(b + 1) * NN + n] = acc[p].f.y + bias;
                }
            }
        }
    }
}

// ---------------- launch ----------------
extern "C" void kernel_launch(void* const* d_in, const int* in_sizes, int n_in,
                              void* d_out, int out_size) {
    const float* x   = (const float*)d_in[0];
    const void*  ei  = d_in[1];
    const float* tf  = (const float*)d_in[2];
    const float* Wl1 = (const float*)d_in[3];
    const float* bl1 = (const float*)d_in[4];
    const float* Wr1 = (const float*)d_in[5];
    const float* Wl2 = (const float*)d_in[6];
    const float* bl2 = (const float*)d_in[7];
    const float* Wr2 = (const float*)d_in[8];
    const float* Wt1 = (const float*)d_in[9];
    const float* bt1 = (const float*)d_in[10];
    const float* Wt2 = (const float*)d_in[11];
    const float* bt2 = (const float*)d_in[12];
    const float* Wc1 = (const float*)d_in[13];
    const float* bc1 = (const float*)d_in[14];
    const float* Wc2 = (const float*)d_in[15];
    const float* bc2 = (const float*)d_in[16];
    float* out = (float*)d_out;

    k_all<<<GRID, NT>>>(x, ei, tf, Wl1, bl1, Wr1, Wl2, bl2, Wr2,
                        Wt1, bt1, Wt2, bt2, Wc1, bc1, Wc2, bc2, out);
}

// round 4
// speedup vs baseline: 1.4144x; 1.4144x over previous
#include <cuda_runtime.h>

#define NN     5000
#define NE     160000
#define HID    64
#define BATCH  512

// ---------------- scratch (device globals; zero-init at module load) ----------------
__device__ int   g_cnt[NN];            // re-zeroed by k_final each call
__device__ int   g_rowptr[NN + 1];
__device__ int   g_cur[NN];
__device__ int   g_esrc[NE];
__device__ __align__(16) float g_h1[NN * HID];
__device__ __align__(16) float g_hp[5120 * HID];   // rows [5000,5120) stay zero forever
__device__ __align__(16) float g_tpT[HID * BATCH]; // transposed: [h][b]

union U64 { unsigned long long u; float2 f; };

__device__ __forceinline__ unsigned long long pack2(float a, float b) {
    unsigned long long r;
    asm("mov.b64 %0, {%1, %2};" : "=l"(r) : "f"(a), "f"(b));
    return r;
}

// per-block edge dtype detection: OR of 256 odd u32 words of this block's slice.
// int64 data -> all high words of values <5000 are 0. int32 -> nonzero w.p. 1-5000^-256.
__device__ __forceinline__ int block_detect_i32(const unsigned* __restrict__ w, int e0) {
    __shared__ unsigned s_or[8];
    __shared__ int s_i32;
    int tid = threadIdx.x;
    unsigned odd = w[2 * (e0 + tid) + 1];
    odd = __reduce_or_sync(0xffffffffu, odd);
    if ((tid & 31) == 0) s_or[tid >> 5] = odd;
    __syncthreads();
    if (tid == 0) {
        unsigned a = 0;
#pragma unroll
        for (int i = 0; i < 8; i++) a |= s_or[i];
        s_i32 = (a != 0);
    }
    __syncthreads();
    return s_i32;
}

// ---------------- 1) degree histogram (grid 625 x 256, exact) ----------------
__global__ void __launch_bounds__(256) k_hist(const void* __restrict__ ei) {
    int e = blockIdx.x * 256 + threadIdx.x;
    int i32 = block_detect_i32((const unsigned*)ei, blockIdx.x * 256);
    int d = i32 ? ((const int*)ei)[NE + e] : (int)((const long long*)ei)[NE + e];
    atomicAdd(&g_cnt[d], 1);
}

// ---------------- 2) rowptr scan (1 block, 1024 thr, warp-shuffle scan) ----------------
__global__ void __launch_bounds__(1024) k_scan() {
    __shared__ int wsum[32];
    int t = threadIdx.x, lane = t & 31, wid = t >> 5;
    int base = t * 5;
    int c[5], s = 0;
#pragma unroll
    for (int i = 0; i < 5; i++) {
        int idx = base + i;
        c[i] = (idx < NN) ? g_cnt[idx] : 0;
        s += c[i];
    }
    int v = s;
#pragma unroll
    for (int off = 1; off < 32; off <<= 1) {
        int u = __shfl_up_sync(0xffffffffu, v, off);
        if (lane >= off) v += u;
    }
    if (lane == 31) wsum[wid] = v;
    __syncthreads();
    if (wid == 0) {
        int z = wsum[lane];
#pragma unroll
        for (int off = 1; off < 32; off <<= 1) {
            int u = __shfl_up_sync(0xffffffffu, z, off);
            if (lane >= off) z += u;
        }
        wsum[lane] = z;
    }
    __syncthreads();
    int run = (v - s) + (wid ? wsum[wid - 1] : 0);   // exclusive prefix
#pragma unroll
    for (int i = 0; i < 5; i++) {
        int idx = base + i;
        if (idx < NN) {
            g_rowptr[idx] = run;
            g_cur[idx]    = run;
            run += c[i];
        } else if (idx == NN) {
            g_rowptr[NN] = run;
        }
    }
}

// -------- task MLP, one warp per batch, shuffle-based --------
__device__ __forceinline__ void do_task(int b, int lane, const float* __restrict__ tf,
                                        const float* __restrict__ Wt1, const float* __restrict__ bt1,
                                        const float* __restrict__ Wt2, const float* __restrict__ bt2,
                                        const float* __restrict__ Wc1, const float* __restrict__ bc1) {
    float4 f = *(const float4*)(tf + (size_t)b * 4);
    int o0 = lane, o1 = lane + 32;
    float a0 = bt1[o0] + Wt1[o0*4]*f.x + Wt1[o0*4+1]*f.y + Wt1[o0*4+2]*f.z + Wt1[o0*4+3]*f.w;
    float a1 = bt1[o1] + Wt1[o1*4]*f.x + Wt1[o1*4+1]*f.y + Wt1[o1*4+2]*f.z + Wt1[o1*4+3]*f.w;
    a0 = fmaxf(a0, 0.f); a1 = fmaxf(a1, 0.f);

    float c0 = bt2[o0], c1 = bt2[o1];
#pragma unroll
    for (int h = 0; h < 32; h++) {
        float v = __shfl_sync(0xffffffffu, a0, h);
        c0 += Wt2[o0*64 + h] * v;
        c1 += Wt2[o1*64 + h] * v;
    }
#pragma unroll
    for (int h = 0; h < 32; h++) {
        float v = __shfl_sync(0xffffffffu, a1, h);
        c0 += Wt2[o0*64 + 32 + h] * v;
        c1 += Wt2[o1*64 + 32 + h] * v;
    }
    float d0 = bc1[o0], d1 = bc1[o1];
#pragma unroll
    for (int h = 0; h < 32; h++) {
        float v = __shfl_sync(0xffffffffu, c0, h);
        d0 += Wc1[o0*128 + 64 + h] * v;
        d1 += Wc1[o1*128 + 64 + h] * v;
    }
#pragma unroll
    for (int h = 0; h < 32; h++) {
        float v = __shfl_sync(0xffffffffu, c1, h);
        d0 += Wc1[o0*128 + 96 + h] * v;
        d1 += Wc1[o1*128 + 96 + h] * v;
    }
    g_tpT[o0 * BATCH + b] = d0;
    g_tpT[o1 * BATCH + b] = d1;
}

// ---------------- 3) CSR fill (blocks 0..624) + task MLP (blocks 625..688) ----------------
__global__ void __launch_bounds__(256) k_fill_task(
        const void* __restrict__ ei, const float* __restrict__ tf,
        const float* __restrict__ Wt1, const float* __restrict__ bt1,
        const float* __restrict__ Wt2, const float* __restrict__ bt2,
        const float* __restrict__ Wc1, const float* __restrict__ bc1) {
    int bx = blockIdx.x;
    if (bx >= 625) {
        int b = (bx - 625) * 8 + (threadIdx.x >> 5);
        do_task(b, threadIdx.x & 31, tf, Wt1, bt1, Wt2, bt2, Wc1, bc1);
        return;
    }
    int e = bx * 256 + threadIdx.x;
    int i32 = block_detect_i32((const unsigned*)ei, bx * 256);
    int s, d;
    if (i32) { const int* p = (const int*)ei; s = p[e]; d = p[NE + e]; }
    else     { const long long* p = (const long long*)ei; s = (int)p[e]; d = (int)p[NE + e]; }
    g_esrc[atomicAdd(&g_cur[d], 1)] = s;
}

// ---------------- 4) layer-1 SAGE: warp per node (grid 625 x 256) ----------------
__global__ void __launch_bounds__(256) k_l1(const float* __restrict__ x,
                                            const float* __restrict__ Wl1,
                                            const float* __restrict__ bl1,
                                            const float* __restrict__ Wr1) {
    int n    = blockIdx.x * 8 + (threadIdx.x >> 5);
    int lane = threadIdx.x & 31;
    int start = g_rowptr[n], end = g_rowptr[n + 1];
    float4 a = make_float4(0.f, 0.f, 0.f, 0.f);
    for (int e = start + lane; e < end; e += 32) {
        float4 xv = *(const float4*)(x + (size_t)g_esrc[e] * 4);
        a.x += xv.x; a.y += xv.y; a.z += xv.z; a.w += xv.w;
    }
#pragma unroll
    for (int off = 16; off; off >>= 1) {
        a.x += __shfl_xor_sync(0xffffffffu, a.x, off);
        a.y += __shfl_xor_sync(0xffffffffu, a.y, off);
        a.z += __shfl_xor_sync(0xffffffffu, a.z, off);
        a.w += __shfl_xor_sync(0xffffffffu, a.w, off);
    }
    float invd = 1.f / fmaxf((float)(end - start), 1.f);
    float m0 = a.x*invd, m1 = a.y*invd, m2 = a.z*invd, m3 = a.w*invd;
    float4 xn = *(const float4*)(x + (size_t)n * 4);
#pragma unroll
    for (int k = 0; k < 2; k++) {
        int o = lane + 32 * k;
        float v = bl1[o]
                + Wl1[o*4]*m0 + Wl1[o*4+1]*m1 + Wl1[o*4+2]*m2 + Wl1[o*4+3]*m3
                + Wr1[o*4]*xn.x + Wr1[o*4+1]*xn.y + Wr1[o*4+2]*xn.z + Wr1[o*4+3]*xn.w;
        g_h1[n*64 + o] = fmaxf(v, 0.f);
    }
}

// ---------------- 5) fused layer-2 SAGE + h_part projection ----------------
// 512 threads = 8 groups of 64; grid 313, 2 sweeps. Dyn smem 53248 B.
#define L2_GRID 313
__global__ void __launch_bounds__(512) k_l2hp(const float* __restrict__ Wl2,
                                              const float* __restrict__ bl2,
                                              const float* __restrict__ Wr2,
                                              const float* __restrict__ Wc1) {
    extern __shared__ float sm[];
    float* sWl   = sm;                 // [h][o] = Wl2[o][h]
    float* sWr   = sm + 4096;
    float* sWc   = sm + 8192;          // [h][o] = Wc1[o][h] (h-part cols)
    float* sMean = sm + 12288;         // [8][64]
    float* sX    = sm + 12800;         // [8][64]
    int tid = threadIdx.x;
    int g = tid >> 6, o = tid & 63;
    for (int idx = tid; idx < 4096; idx += 512) {
        int r = idx >> 6, c = idx & 63;                 // r = out, c = in
        sWl[c*64 + r] = Wl2[idx];
        sWr[c*64 + r] = Wr2[idx];
        sWc[c*64 + r] = Wc1[r*128 + c];
    }
    float bias = bl2[o];
    __syncthreads();
#pragma unroll
    for (int sw = 0; sw < 2; sw++) {
        int n = (sw * L2_GRID + blockIdx.x) * 8 + g;
        bool ok = (n < NN);
        float h2 = 0.f;
        if (ok) {
            int st = g_rowptr[n], en = g_rowptr[n + 1];
            float s = 0.f;
#pragma unroll 8
            for (int e = st; e < en; e++) s += g_h1[g_esrc[e]*64 + o];
            sMean[g*64 + o] = s / fmaxf((float)(en - st), 1.f);
            sX[g*64 + o]    = g_h1[n*64 + o];
        }
        __syncthreads();
        if (ok) {
            float acc = bias;
#pragma unroll
            for (int h = 0; h < 64; h++)
                acc += sWl[h*64 + o] * sMean[g*64 + h] + sWr[h*64 + o] * sX[g*64 + h];
            h2 = fmaxf(acc, 0.f);
        }
        __syncthreads();
        if (ok) sMean[g*64 + o] = h2;
        __syncthreads();
        if (ok) {
            float hp = 0.f;
#pragma unroll
            for (int h = 0; h < 64; h++)
                hp += sWc[h*64 + o] * sMean[g*64 + h];
            g_hp[n*64 + o] = hp;
        }
        __syncthreads();
    }
}

// ---------------- 6) final scores + re-zero g_cnt. grid (40,8) x 256. ----------------
// Dyn smem: hp 64x129 + tp 64x64 + w2 64 -> 49920 B.
__global__ void __launch_bounds__(256) k_final(const float* __restrict__ Wc2,
                                               const float* __restrict__ bc2,
                                               float* __restrict__ out) {
    extern __shared__ float smf[];
    float* s_hp = smf;                       // [h][nl] pad 129
    float* s_tp = smf + 64 * 129;            // [h][bl] 64 wide
    unsigned long long* s_w2 = (unsigned long long*)(smf + 64 * 129 + 64 * 64);
    int tid = threadIdx.x;

    // side job: re-zero g_cnt for the next replay
    int bid = blockIdx.y * gridDim.x + blockIdx.x;
    if (bid < 20) {
        int i = bid * 256 + tid;
        if (i < NN) g_cnt[i] = 0;
    }

    int n0 = blockIdx.x * 128, b0 = blockIdx.y * 64;
    for (int idx = tid; idx < 8192; idx += 256) {
        int r = idx >> 6, h = idx & 63;                  // coalesced global, conflict-free smem
        s_hp[h*129 + r] = g_hp[(size_t)(n0 + r) * 64 + h];
    }
    for (int idx = tid; idx < 4096; idx += 256) {
        int h = idx >> 6, r = idx & 63;                  // g_tpT is [h][b]: coalesced
        s_tp[h*64 + r] = g_tpT[h * BATCH + b0 + r];
    }
    if (tid < 64) { float w = Wc2[tid]; s_w2[tid] = pack2(w, w); }
    __syncthreads();

    int nl = tid & 127, q = tid >> 7;                    // q in {0,1}: batch half
    U64 acc[16];
#pragma unroll
    for (int p = 0; p < 16; p++) acc[p].u = 0ull;

    for (int h = 0; h < 64; h++) {
        float hv = s_hp[h*129 + nl];
        unsigned long long hv2 = pack2(hv, hv);
        unsigned long long w2  = s_w2[h];
        const unsigned long long* tp = (const unsigned long long*)(s_tp + h*64 + q*32);
#pragma unroll
        for (int p = 0; p < 16; p++) {
            U64 a;
            asm("add.rn.f32x2 %0, %1, %2;" : "=l"(a.u) : "l"(tp[p]), "l"(hv2));
            a.f.x = fmaxf(a.f.x, 0.f);
            a.f.y = fmaxf(a.f.y, 0.f);
            asm("fma.rn.f32x2 %0, %1, %2, %0;" : "+l"(acc[p].u) : "l"(a.u), "l"(w2));
        }
    }

    int n = n0 + nl;
    if (n < NN) {
        float bias = bc2[0];
#pragma unroll
        for (int p = 0; p < 16; p++) {
            int b = b0 + q*32 + 2*p;
            out[(size_t)b       * NN + n] = acc[p].f.x + bias;
            out[(size_t)(b + 1) * NN + n] = acc[p].f.y + bias;
        }
    }
}

// ---------------- launch ----------------
extern "C" void kernel_launch(void* const* d_in, const int* in_sizes, int n_in,
                              void* d_out, int out_size) {
    const float* x   = (const float*)d_in[0];
    const void*  ei  = d_in[1];
    const float* tf  = (const float*)d_in[2];
    const float* Wl1 = (const float*)d_in[3];
    const float* bl1 = (const float*)d_in[4];
    const float* Wr1 = (const float*)d_in[5];
    const float* Wl2 = (const float*)d_in[6];
    const float* bl2 = (const float*)d_in[7];
    const float* Wr2 = (const float*)d_in[8];
    const float* Wt1 = (const float*)d_in[9];
    const float* bt1 = (const float*)d_in[10];
    const float* Wt2 = (const float*)d_in[11];
    const float* bt2 = (const float*)d_in[12];
    const float* Wc1 = (const float*)d_in[13];
    const float* bc1 = (const float*)d_in[14];
    const float* Wc2 = (const float*)d_in[15];
    const float* bc2 = (const float*)d_in[16];
    float* out = (float*)d_out;

    static bool attr_set = false;
    if (!attr_set) {
        cudaFuncSetAttribute(k_l2hp,  cudaFuncAttributeMaxDynamicSharedMemorySize, 53248);
        cudaFuncSetAttribute(k_final, cudaFuncAttributeMaxDynamicSharedMemorySize, 49920);
        attr_set = true;
    }

    k_hist     <<<625, 256>>>(ei);
    k_scan     <<<1, 1024>>>();
    k_fill_task<<<689, 256>>>(ei, tf, Wt1, bt1, Wt2, bt2, Wc1, bc1);
    k_l1       <<<625, 256>>>(x, Wl1, bl1, Wr1);
    k_l2hp     <<<L2_GRID, 512, 53248>>>(Wl2, bl2, Wr2, Wc1);
    k_final    <<<dim3(40, 8), 256, 49920>>>(Wc2, bc2, out);
}